// round 2
// baseline (speedup 1.0000x reference)
#include <cuda_runtime.h>
#include <math.h>

#define NN    50000
#define EE    400000
#define HH    128
#define NRBFN 20
#define NOUT  384          // 3*H
#define FCUT  8.0f
#define NT    4096         // distance table resolution

// Scratch (device globals: allocation-free rule)
__device__ float g_spn[NN * NOUT];   // per-node scalar-MLP output, 76.8 MB
__device__ float g_tab[NT * NOUT];   // W(d) table, 6.3 MB (L2-resident)

__device__ __forceinline__ float silu_f(float x) {
    return x / (1.0f + __expf(-x));
}

// ---------------------------------------------------------------------------
// Kernel 0: out = [s ; v]  (segment sums accumulate on top via atomics)
// ---------------------------------------------------------------------------
__global__ void init_out_kernel(const float* __restrict__ s,
                                const float* __restrict__ v,
                                float* __restrict__ out) {
    int i = blockIdx.x * blockDim.x + threadIdx.x;   // float4 index
    const int nS4 = NN * HH / 4;          // 1.6M
    const int nT4 = NN * HH;              // 6.4M float4 total (N*512/4)
    if (i < nS4) {
        ((float4*)out)[i] = ((const float4*)s)[i];
    } else if (i < nT4) {
        ((float4*)out)[i] = ((const float4*)v)[i - nS4];
    }
}

// ---------------------------------------------------------------------------
// Kernel 1: build W(d) table. 8 rows per block, 128 threads.
// W(d) = silu(feat(d) @ w1^T + b1) @ w2^T + b2,  feat depends only on d.
// ---------------------------------------------------------------------------
__global__ void build_tab_kernel(const float* __restrict__ rbf_c,
                                 const float* __restrict__ rbf_w,
                                 const float* __restrict__ w1,   // [128,20]
                                 const float* __restrict__ b1,   // [128]
                                 const float* __restrict__ w2,   // [384,128]
                                 const float* __restrict__ b2) { // [384]
    __shared__ float feat_sm[8][NRBFN];
    __shared__ float g_sm[8][HH];
    const int tid  = threadIdx.x;        // 128
    const int row0 = blockIdx.x * 8;

    for (int idx = tid; idx < 8 * NRBFN; idx += 128) {
        int r = idx / NRBFN, i = idx % NRBFN;
        float d   = (row0 + r) * (FCUT / (float)(NT - 1));
        float x   = d / FCUT;
        float env = (x < 1.0f) ? 0.5f * (__cosf(3.14159265358979f * x) + 1.0f) : 0.0f;
        float df  = d - rbf_c[i];
        feat_sm[r][i] = __expf(-fabsf(rbf_w[i]) * df * df) * env;
    }
    __syncthreads();

    float wrow[NRBFN];
    #pragma unroll
    for (int i = 0; i < NRBFN; i++) wrow[i] = w1[tid * NRBFN + i];
    float bb = b1[tid];
    #pragma unroll
    for (int r = 0; r < 8; r++) {
        float a = bb;
        #pragma unroll
        for (int i = 0; i < NRBFN; i++) a += feat_sm[r][i] * wrow[i];
        g_sm[r][tid] = silu_f(a);
    }
    __syncthreads();

    float a0[8], a1[8], a2[8];
    #pragma unroll
    for (int r = 0; r < 8; r++) { a0[r] = 0.f; a1[r] = 0.f; a2[r] = 0.f; }
    const float* w2r0 = w2 + (tid)       * HH;
    const float* w2r1 = w2 + (tid + 128) * HH;
    const float* w2r2 = w2 + (tid + 256) * HH;
    for (int k = 0; k < HH; k++) {
        float x0 = w2r0[k], x1 = w2r1[k], x2 = w2r2[k];
        #pragma unroll
        for (int r = 0; r < 8; r++) {
            float h = g_sm[r][k];
            a0[r] += h * x0; a1[r] += h * x1; a2[r] += h * x2;
        }
    }
    float c0 = b2[tid], c1 = b2[tid + 128], c2 = b2[tid + 256];
    #pragma unroll
    for (int r = 0; r < 8; r++) {
        float* o = g_tab + (row0 + r) * NOUT;
        o[tid]       = a0[r] + c0;
        o[tid + 128] = a1[r] + c1;
        o[tid + 256] = a2[r] + c2;
    }
}

// ---------------------------------------------------------------------------
// Kernel 2: per-node scalar MLP  sp_node = silu(s@phi1^T+b1)@phi2^T+b2
// 16 nodes per block, 128 threads. fp32 SIMT (tensor-core candidate later).
// ---------------------------------------------------------------------------
__global__ void node_mlp_kernel(const float* __restrict__ s,
                                const float* __restrict__ w1,   // [128,128]
                                const float* __restrict__ b1,
                                const float* __restrict__ w2,   // [384,128]
                                const float* __restrict__ b2) {
    __shared__ __align__(16) float s_sm[16][HH];
    __shared__ __align__(16) float h_sm[16][HH];
    const int tid = threadIdx.x;   // 128
    const int n0  = blockIdx.x * 16;

    for (int idx = tid; idx < 16 * HH; idx += 128) {
        int r = idx >> 7, k = idx & 127;
        s_sm[r][k] = s[(n0 + r) * HH + k];
    }
    __syncthreads();

    // phase 1: h[r][tid]
    float acc[16];
    #pragma unroll
    for (int r = 0; r < 16; r++) acc[r] = 0.f;
    const float* w1r = w1 + tid * HH;
    for (int k = 0; k < HH; k += 4) {
        float4 w = *(const float4*)(w1r + k);
        #pragma unroll
        for (int r = 0; r < 16; r++) {
            float4 sv = *(const float4*)(&s_sm[r][k]);
            acc[r] += sv.x * w.x + sv.y * w.y + sv.z * w.z + sv.w * w.w;
        }
    }
    float bb = b1[tid];
    #pragma unroll
    for (int r = 0; r < 16; r++) h_sm[r][tid] = silu_f(acc[r] + bb);
    __syncthreads();

    // phase 2: 3 output rows per thread
    float a0[16], a1[16], a2[16];
    #pragma unroll
    for (int r = 0; r < 16; r++) { a0[r] = 0.f; a1[r] = 0.f; a2[r] = 0.f; }
    const float* w2r0 = w2 + (tid)       * HH;
    const float* w2r1 = w2 + (tid + 128) * HH;
    const float* w2r2 = w2 + (tid + 256) * HH;
    for (int k = 0; k < HH; k += 4) {
        float4 x0 = *(const float4*)(w2r0 + k);
        float4 x1 = *(const float4*)(w2r1 + k);
        float4 x2 = *(const float4*)(w2r2 + k);
        #pragma unroll
        for (int r = 0; r < 16; r++) {
            float4 h = *(const float4*)(&h_sm[r][k]);
            a0[r] += h.x * x0.x + h.y * x0.y + h.z * x0.z + h.w * x0.w;
            a1[r] += h.x * x1.x + h.y * x1.y + h.z * x1.z + h.w * x1.w;
            a2[r] += h.x * x2.x + h.y * x2.y + h.z * x2.z + h.w * x2.w;
        }
    }
    float c0 = b2[tid], c1 = b2[tid + 128], c2 = b2[tid + 256];
    #pragma unroll
    for (int r = 0; r < 16; r++) {
        float* o = g_spn + (n0 + r) * NOUT;
        o[tid]       = a0[r] + c0;
        o[tid + 128] = a1[r] + c1;
        o[tid + 256] = a2[r] + c2;
    }
}

// ---------------------------------------------------------------------------
// Kernel 3: per-edge message + atomic scatter. One warp per edge.
// edge_index is int32 (JAX x64 disabled downgrades int64 -> int32).
// ---------------------------------------------------------------------------
__global__ void edge_kernel(const float* __restrict__ pos,
                            const float* __restrict__ v,
                            const int* __restrict__ ei,
                            float* __restrict__ out) {
    const int gw   = (blockIdx.x * blockDim.x + threadIdx.x) >> 5;
    const int lane = threadIdx.x & 31;
    if (gw >= EE) return;

    const int src = ei[gw];
    const int dst = ei[EE + gw];

    float rx = pos[dst * 3 + 0] - pos[src * 3 + 0];
    float ry = pos[dst * 3 + 1] - pos[src * 3 + 1];
    float rz = pos[dst * 3 + 2] - pos[src * 3 + 2];
    float d  = fmaxf(sqrtf(rx * rx + ry * ry + rz * rz), 1e-6f);
    float iv = 1.0f / d;
    float ux = rx * iv, uy = ry * iv, uz = rz * iv;

    // table interpolation coordinates
    float t = fminf(d, FCUT) * ((float)(NT - 1) / FCUT);
    int   i0 = (int)t;
    if (i0 > NT - 2) i0 = NT - 2;
    float f = t - (float)i0;

    const float* t0 = g_tab + i0 * NOUT;
    const float* t1 = t0 + NOUT;
    const float* sp = g_spn + (long long)src * NOUT;
    const float* vs = v + (long long)src * (HH * 3);
    float* out_s = out + (long long)dst * HH;
    float* out_v = out + (long long)NN * HH + (long long)dst * HH * 3;

    #pragma unroll
    for (int j = 0; j < 4; j++) {
        int h = lane + 32 * j;
        float wS  = fmaf(f, t1[h]       - t0[h],       t0[h]);
        float wV1 = fmaf(f, t1[h + 128] - t0[h + 128], t0[h + 128]);
        float wV2 = fmaf(f, t1[h + 256] - t0[h + 256], t0[h + 256]);
        float dS  = sp[h]       * wS;
        float dV1 = sp[h + 128] * wV1;
        float dV2 = sp[h + 256] * wV2;
        atomicAdd(out_s + h, dS);
        float vx = vs[h * 3 + 0], vy = vs[h * 3 + 1], vz = vs[h * 3 + 2];
        float* ov = out_v + h * 3;
        atomicAdd(ov + 0, fmaf(dV1, vx, dV2 * ux));
        atomicAdd(ov + 1, fmaf(dV1, vy, dV2 * uy));
        atomicAdd(ov + 2, fmaf(dV1, vz, dV2 * uz));
    }
}

// ---------------------------------------------------------------------------
extern "C" void kernel_launch(void* const* d_in, const int* in_sizes, int n_in,
                              void* d_out, int out_size) {
    const float* s      = (const float*)d_in[0];
    const float* v      = (const float*)d_in[1];
    const float* pos    = (const float*)d_in[2];
    const float* rbf_c  = (const float*)d_in[3];
    const float* rbf_w  = (const float*)d_in[4];
    const float* phi_w1 = (const float*)d_in[5];
    const float* phi_b1 = (const float*)d_in[6];
    const float* phi_w2 = (const float*)d_in[7];
    const float* phi_b2 = (const float*)d_in[8];
    const float* w_w1   = (const float*)d_in[9];
    const float* w_b1   = (const float*)d_in[10];
    const float* w_w2   = (const float*)d_in[11];
    const float* w_b2   = (const float*)d_in[12];
    const int*   ei     = (const int*)d_in[13];
    float* out = (float*)d_out;

    // 1) out = [s ; v]
    {
        int n4 = NN * HH;               // total float4 count (N*512/4)
        init_out_kernel<<<(n4 + 255) / 256, 256>>>(s, v, out);
    }
    // 2) distance->W table
    build_tab_kernel<<<NT / 8, 128>>>(rbf_c, rbf_w, w_w1, w_b1, w_w2, w_b2);
    // 3) per-node scalar MLP
    node_mlp_kernel<<<NN / 16, 128>>>(s, phi_w1, phi_b1, phi_w2, phi_b2);
    // 4) per-edge messages + scatter
    {
        long long threads = (long long)EE * 32;
        edge_kernel<<<(int)((threads + 255) / 256), 256>>>(pos, v, ei, out);
    }
}